// round 13
// baseline (speedup 1.0000x reference)
#include <cuda_runtime.h>
#include <cuda_bf16.h>
#include <cuda_fp16.h>
#include <cstdint>

// ---------------------------------------------------------------------------
// EigenGIN: 3x GINConv(sum-agg + Linear + ReLU, residual) + projection.
// CSR pull kernels gather from HALF shadow copies (half L2 traffic); self +
// residual stay fp32. BM=64 mma.sync GEMMs (bf16-pair split), pre-transposed
// weights, hierarchical scan, projection fused into layer-2 GEMM.
// ---------------------------------------------------------------------------

#define MAX_NODES 50000
#define MAX_EDGES 800000
#define SCAN_BLOCKS ((MAX_NODES + 1023) / 1024)

__device__ float g_sum[MAX_NODES * 128];
__device__ float g_h0 [MAX_NODES * 128];
__device__ float g_h1 [MAX_NODES * 128];
__device__ __half g_xh [MAX_NODES * 64];    // half shadow of x
__device__ __half g_h0h[MAX_NODES * 128];   // half shadow of h0
__device__ __half g_h1h[MAX_NODES * 128];   // half shadow of h1

__device__ int g_row[MAX_NODES + 1];
__device__ int g_cur[MAX_NODES];
__device__ int g_csr[MAX_EDGES];
__device__ int g_blk[SCAN_BLOCKS];

// WT buffers (bf16 hi/lo, [N][K] layout)
#define WT0_OFF 0
#define WT1_OFF 8192
#define WT2_OFF 24576
#define WTP_OFF 40960
#define WT_TOTAL 45056
#define WT_BLOCKS ((WT_TOTAL + 255) / 256)

__device__ __nv_bfloat16 g_wthi[WT_TOTAL];
__device__ __nv_bfloat16 g_wtlo[WT_TOTAL];

// ===================== helpers ====================
__device__ __forceinline__ uint32_t smem_u32(const void* p) {
    uint32_t a;
    asm("{ .reg .u64 t; cvta.to.shared.u64 t, %1; cvt.u32.u64 %0, t; }"
        : "=r"(a) : "l"(p));
    return a;
}

#define LDMATRIX_X4(R0, R1, R2, R3, ADDR) \
    asm volatile("ldmatrix.sync.aligned.m8n8.x4.shared.b16 {%0,%1,%2,%3}, [%4];" \
                 : "=r"(R0), "=r"(R1), "=r"(R2), "=r"(R3) : "r"(ADDR))

__device__ __forceinline__ void mma_bf16(float* c, const uint32_t* a, const uint32_t* b) {
    asm volatile(
        "mma.sync.aligned.m16n8k16.row.col.f32.bf16.bf16.f32 "
        "{%0,%1,%2,%3}, {%4,%5,%6,%7}, {%8,%9}, {%0,%1,%2,%3};"
        : "+f"(c[0]), "+f"(c[1]), "+f"(c[2]), "+f"(c[3])
        : "r"(a[0]), "r"(a[1]), "r"(a[2]), "r"(a[3]), "r"(b[0]), "r"(b[1]));
}

__device__ __forceinline__ uint32_t pack_bf2(__nv_bfloat16 a, __nv_bfloat16 b) {
    return (uint32_t)__bfloat16_as_ushort(a) | ((uint32_t)__bfloat16_as_ushort(b) << 16);
}
__device__ __forceinline__ void split2(float f, __nv_bfloat16& h, __nv_bfloat16& l) {
    h = __float2bfloat16(f);
    l = __float2bfloat16(f - __bfloat162float(h));
}

// ===================== Prologue kernels ====================
// prep: weight transpose+split | zero cursor | x -> half shadow
__global__ void prep_kernel(const float* __restrict__ W0, const float* __restrict__ W1,
                            const float* __restrict__ W2, const float* __restrict__ Wp,
                            const float* __restrict__ x, __half* __restrict__ xh,
                            __nv_bfloat16* __restrict__ hi, __nv_bfloat16* __restrict__ lo,
                            int* __restrict__ cur, int n_nodes, int cur_blocks)
{
    int b = blockIdx.x;
    if (b < WT_BLOCKS) {
        int i = b * 256 + threadIdx.x;
        if (i >= WT_TOTAL) return;
        const float* W; int K, N, off, local;
        if (i < 8192)       { W = W0; K = 64;  N = 128; off = WT0_OFF; local = i; }
        else if (i < 24576) { W = W1; K = 128; N = 128; off = WT1_OFF; local = i - 8192; }
        else if (i < 40960) { W = W2; K = 128; N = 128; off = WT2_OFF; local = i - 24576; }
        else                { W = Wp; K = 128; N = 32;  off = WTP_OFF; local = i - 40960; }
        int k = local / N, n = local % N;
        __nv_bfloat16 h, l;
        split2(__ldg(&W[local]), h, l);
        hi[off + n * K + k] = h;
        lo[off + n * K + k] = l;
    } else if (b < WT_BLOCKS + cur_blocks) {
        int i = (b - WT_BLOCKS) * 256 + threadIdx.x;
        if (i < n_nodes) cur[i] = 0;
    } else {
        // x -> half: 4 elements per thread
        int i = (b - WT_BLOCKS - cur_blocks) * 256 + threadIdx.x;
        int n4 = n_nodes * 16;  // groups of 4 over n_nodes*64
        if (i < n4) {
            float4 v = __ldg(reinterpret_cast<const float4*>(x) + i);
            __half2 h0 = __floats2half2_rn(v.x, v.y);
            __half2 h1 = __floats2half2_rn(v.z, v.w);
            reinterpret_cast<__half2*>(xh)[i * 2]     = h0;
            reinterpret_cast<__half2*>(xh)[i * 2 + 1] = h1;
        }
    }
}

__global__ void count_kernel(const int* __restrict__ ei, int* __restrict__ counts,
                             int n_edges)
{
    int e = blockIdx.x * blockDim.x + threadIdx.x;
    if (e < n_edges) atomicAdd(&counts[__ldg(&ei[n_edges + e])], 1);
}

__global__ void scan_block(const int* __restrict__ counts, int* __restrict__ excl,
                           int* __restrict__ blk_sums, int n)
{
    __shared__ int sd[1024];
    int tid = threadIdx.x;
    int i = blockIdx.x * 1024 + tid;
    int v = (i < n) ? counts[i] : 0;
    sd[tid] = v;
    __syncthreads();
#pragma unroll
    for (int off = 1; off < 1024; off <<= 1) {
        int tv = (tid >= off) ? sd[tid - off] : 0;
        __syncthreads();
        sd[tid] += tv;
        __syncthreads();
    }
    if (i < n) excl[i] = sd[tid] - v;
    if (tid == 1023) blk_sums[blockIdx.x] = sd[1023];
}

__global__ void scan_sums(int* __restrict__ blk_sums, int* __restrict__ row_start,
                          int nblocks, int n)
{
    __shared__ int sd[64];
    int tid = threadIdx.x;
    int v = (tid < nblocks) ? blk_sums[tid] : 0;
    sd[tid] = v;
    __syncthreads();
#pragma unroll
    for (int off = 1; off < 64; off <<= 1) {
        int tv = (tid >= off) ? sd[tid - off] : 0;
        __syncthreads();
        sd[tid] += tv;
        __syncthreads();
    }
    if (tid < nblocks) blk_sums[tid] = sd[tid] - v;
    if (tid == 63) row_start[n] = sd[63];
}

__global__ void scan_add(int* __restrict__ excl, const int* __restrict__ blk_sums,
                         int* __restrict__ cursor, int n)
{
    int i = blockIdx.x * 1024 + threadIdx.x;
    if (i < n) {
        int v = excl[i] + blk_sums[blockIdx.x];
        excl[i] = v;
        cursor[i] = v;
    }
}

__global__ void fill_kernel(const int* __restrict__ ei, int* __restrict__ cursor,
                            int* __restrict__ csr_src, int n_edges)
{
    int e = blockIdx.x * blockDim.x + threadIdx.x;
    if (e < n_edges) {
        int d = __ldg(&ei[n_edges + e]);
        int s = __ldg(&ei[e]);
        int pos = atomicAdd(&cursor[d], 1);
        csr_src[pos] = s;
    }
}

// ===================== Pull aggregation (half gather, fp32 self/acc) =======
__global__ void pull128_kernel(const float* __restrict__ feat,
                               const __half* __restrict__ feath,
                               const int* __restrict__ row_start,
                               const int* __restrict__ csr_src,
                               float* __restrict__ out, int n_nodes)
{
    int node = (blockIdx.x * blockDim.x + threadIdx.x) >> 5;
    int lane = threadIdx.x & 31;
    if (node >= n_nodes) return;
    int e0 = __ldg(&row_start[node]);
    int e1 = __ldg(&row_start[node + 1]);
    // self term in fp32
    float4 acc = __ldg(reinterpret_cast<const float4*>(feat + (size_t)node * 128) + lane);
    int e = e0;
    for (; e + 1 < e1; e += 2) {
        int s0 = __ldg(&csr_src[e]);
        int s1 = __ldg(&csr_src[e + 1]);
        uint2 r0 = __ldg(reinterpret_cast<const uint2*>(feath + (size_t)s0 * 128) + lane);
        uint2 r1 = __ldg(reinterpret_cast<const uint2*>(feath + (size_t)s1 * 128) + lane);
        float2 a0 = __half22float2(*reinterpret_cast<__half2*>(&r0.x));
        float2 a1 = __half22float2(*reinterpret_cast<__half2*>(&r0.y));
        float2 b0 = __half22float2(*reinterpret_cast<__half2*>(&r1.x));
        float2 b1 = __half22float2(*reinterpret_cast<__half2*>(&r1.y));
        acc.x += a0.x + b0.x; acc.y += a0.y + b0.y;
        acc.z += a1.x + b1.x; acc.w += a1.y + b1.y;
    }
    if (e < e1) {
        int s = __ldg(&csr_src[e]);
        uint2 r0 = __ldg(reinterpret_cast<const uint2*>(feath + (size_t)s * 128) + lane);
        float2 a0 = __half22float2(*reinterpret_cast<__half2*>(&r0.x));
        float2 a1 = __half22float2(*reinterpret_cast<__half2*>(&r0.y));
        acc.x += a0.x; acc.y += a0.y; acc.z += a1.x; acc.w += a1.y;
    }
    *reinterpret_cast<float4*>(out + (size_t)node * 128 + lane * 4) = acc;
}

__global__ void pull64_kernel(const float* __restrict__ feat,
                              const __half* __restrict__ feath,
                              const int* __restrict__ row_start,
                              const int* __restrict__ csr_src,
                              float* __restrict__ out, int n_nodes)
{
    int gw   = (blockIdx.x * blockDim.x + threadIdx.x) >> 5;
    int lane = threadIdx.x & 31;
    int node = gw * 2 + (lane >> 4);
    int sub  = lane & 15;
    if (node >= n_nodes) return;
    int e0 = __ldg(&row_start[node]);
    int e1 = __ldg(&row_start[node + 1]);
    float4 acc = __ldg(reinterpret_cast<const float4*>(feat + (size_t)node * 64) + sub);
    int e = e0;
    for (; e + 1 < e1; e += 2) {
        int s0 = __ldg(&csr_src[e]);
        int s1 = __ldg(&csr_src[e + 1]);
        uint2 r0 = __ldg(reinterpret_cast<const uint2*>(feath + (size_t)s0 * 64) + sub);
        uint2 r1 = __ldg(reinterpret_cast<const uint2*>(feath + (size_t)s1 * 64) + sub);
        float2 a0 = __half22float2(*reinterpret_cast<__half2*>(&r0.x));
        float2 a1 = __half22float2(*reinterpret_cast<__half2*>(&r0.y));
        float2 b0 = __half22float2(*reinterpret_cast<__half2*>(&r1.x));
        float2 b1 = __half22float2(*reinterpret_cast<__half2*>(&r1.y));
        acc.x += a0.x + b0.x; acc.y += a0.y + b0.y;
        acc.z += a1.x + b1.x; acc.w += a1.y + b1.y;
    }
    if (e < e1) {
        int s = __ldg(&csr_src[e]);
        uint2 r0 = __ldg(reinterpret_cast<const uint2*>(feath + (size_t)s * 64) + sub);
        float2 a0 = __half22float2(*reinterpret_cast<__half2*>(&r0.x));
        float2 a1 = __half22float2(*reinterpret_cast<__half2*>(&r0.y));
        acc.x += a0.x; acc.y += a0.y; acc.z += a1.x; acc.w += a1.y;
    }
    *reinterpret_cast<float4*>(out + (size_t)node * 64 + sub * 4) = acc;
}

// ===================== mma.sync GEMM (BM=64) ====================
// OUT fp32; OUTH (optional) half shadow for next layer's gather.
template <int K, int N, int WM, bool RELU, bool RESID>
__global__ __launch_bounds__(256)
void gemm_mma(const float* __restrict__ X,
              const __nv_bfloat16* __restrict__ WT_hi,
              const __nv_bfloat16* __restrict__ WT_lo,
              const float* __restrict__ Bv,
              const float* __restrict__ RES,
              float* __restrict__ OUT,
              __half* __restrict__ OUTH,
              int nrows)
{
    constexpr int BM = 64;
    constexpr int SK = K + 8;
    constexpr int WNW = 8 / WM;
    constexpr int MT = BM / WM / 16;
    constexpr int WN = N / WNW;
    constexpr int NT = WN / 8;
    constexpr int KS = K / 16;

    extern __shared__ __nv_bfloat16 smem[];
    __nv_bfloat16* Ah = smem;
    __nv_bfloat16* Al = Ah + BM * SK;
    __nv_bfloat16* Bh = Al + BM * SK;
    __nv_bfloat16* Bl = Bh + (size_t)N * SK;

    const int t = threadIdx.x;
    const int lane = t & 31;
    const int wid = t >> 5;
    const int wm = wid % WM;
    const int wn = wid / WM;
    const int row0 = blockIdx.x * BM;

    for (int i = t; i < N * K / 8; i += 256) {
        int n = (i * 8) / K;
        int k = (i * 8) % K;
        uint4 vh = __ldg(reinterpret_cast<const uint4*>(WT_hi) + i);
        uint4 vl = __ldg(reinterpret_cast<const uint4*>(WT_lo) + i);
        *reinterpret_cast<uint4*>(&Bh[n * SK + k]) = vh;
        *reinterpret_cast<uint4*>(&Bl[n * SK + k]) = vl;
    }

    for (int i = t; i < BM * K / 4; i += 256) {
        int row = (i * 4) / K;
        int col = (i * 4) % K;
        float4 v = make_float4(0.f, 0.f, 0.f, 0.f);
        int gr = row0 + row;
        if (gr < nrows)
            v = __ldg(reinterpret_cast<const float4*>(X + (size_t)gr * K) + (col >> 2));
        __nv_bfloat16 h0, h1, h2, h3, l0, l1, l2, l3;
        split2(v.x, h0, l0); split2(v.y, h1, l1);
        split2(v.z, h2, l2); split2(v.w, h3, l3);
        int o = row * SK + col;
        *reinterpret_cast<uint32_t*>(&Ah[o])     = pack_bf2(h0, h1);
        *reinterpret_cast<uint32_t*>(&Ah[o + 2]) = pack_bf2(h2, h3);
        *reinterpret_cast<uint32_t*>(&Al[o])     = pack_bf2(l0, l1);
        *reinterpret_cast<uint32_t*>(&Al[o + 2]) = pack_bf2(l2, l3);
    }
    __syncthreads();

    float acc[MT][NT][4] = {};
    for (int ks = 0; ks < KS; ks++) {
        const int k0 = ks * 16;
        const int tt = lane >> 3;
        const int tr = lane & 7;

        uint32_t a[MT][2][4];
#pragma unroll
        for (int mt = 0; mt < MT; mt++) {
            int r = wm * (MT * 16) + mt * 16 + (tt & 1) * 8 + tr;
            int c = k0 + (tt >> 1) * 8;
            LDMATRIX_X4(a[mt][0][0], a[mt][0][1], a[mt][0][2], a[mt][0][3],
                        smem_u32(&Ah[r * SK + c]));
            LDMATRIX_X4(a[mt][1][0], a[mt][1][1], a[mt][1][2], a[mt][1][3],
                        smem_u32(&Al[r * SK + c]));
        }

        uint32_t b[NT][2][2];
#pragma unroll
        for (int p = 0; p < NT / 2; p++) {
            int n = wn * WN + p * 16 + (tt >> 1) * 8 + tr;
            int c = k0 + (tt & 1) * 8;
            uint32_t r0, r1, r2, r3;
            LDMATRIX_X4(r0, r1, r2, r3, smem_u32(&Bh[n * SK + c]));
            b[2*p][0][0] = r0; b[2*p][0][1] = r1;
            b[2*p+1][0][0] = r2; b[2*p+1][0][1] = r3;
            LDMATRIX_X4(r0, r1, r2, r3, smem_u32(&Bl[n * SK + c]));
            b[2*p][1][0] = r0; b[2*p][1][1] = r1;
            b[2*p+1][1][0] = r2; b[2*p+1][1][1] = r3;
        }

#pragma unroll
        for (int mt = 0; mt < MT; mt++)
#pragma unroll
            for (int nt = 0; nt < NT; nt++)
                mma_bf16(acc[mt][nt], a[mt][0], b[nt][0]);
#pragma unroll
        for (int mt = 0; mt < MT; mt++)
#pragma unroll
            for (int nt = 0; nt < NT; nt++)
                mma_bf16(acc[mt][nt], a[mt][0], b[nt][1]);
#pragma unroll
        for (int mt = 0; mt < MT; mt++)
#pragma unroll
            for (int nt = 0; nt < NT; nt++)
                mma_bf16(acc[mt][nt], a[mt][1], b[nt][0]);
    }

#pragma unroll
    for (int mt = 0; mt < MT; mt++) {
        int r_lo = row0 + wm * (MT * 16) + mt * 16 + (lane >> 2);
        int r_hi = r_lo + 8;
#pragma unroll
        for (int nt = 0; nt < NT; nt++) {
            int col = wn * WN + nt * 8 + (lane & 3) * 2;
            float bi0 = __ldg(&Bv[col]);
            float bi1 = __ldg(&Bv[col + 1]);
            if (r_lo < nrows) {
                float o0 = acc[mt][nt][0] + bi0;
                float o1 = acc[mt][nt][1] + bi1;
                if (RELU) { o0 = fmaxf(o0, 0.f); o1 = fmaxf(o1, 0.f); }
                if (RESID) {
                    float2 rr = __ldg(reinterpret_cast<const float2*>(RES + (size_t)r_lo * N + col));
                    o0 += rr.x; o1 += rr.y;
                }
                *reinterpret_cast<float2*>(OUT + (size_t)r_lo * N + col) = make_float2(o0, o1);
                if (OUTH)
                    *reinterpret_cast<__half2*>(OUTH + (size_t)r_lo * N + col) =
                        __floats2half2_rn(o0, o1);
            }
            if (r_hi < nrows) {
                float o0 = acc[mt][nt][2] + bi0;
                float o1 = acc[mt][nt][3] + bi1;
                if (RELU) { o0 = fmaxf(o0, 0.f); o1 = fmaxf(o1, 0.f); }
                if (RESID) {
                    float2 rr = __ldg(reinterpret_cast<const float2*>(RES + (size_t)r_hi * N + col));
                    o0 += rr.x; o1 += rr.y;
                }
                *reinterpret_cast<float2*>(OUT + (size_t)r_hi * N + col) = make_float2(o0, o1);
                if (OUTH)
                    *reinterpret_cast<__half2*>(OUTH + (size_t)r_hi * N + col) =
                        __floats2half2_rn(o0, o1);
            }
        }
    }
}

// ===================== Fused layer-2 GEMM + projection ====================
__global__ __launch_bounds__(256)
void gemm_l2_proj(const float* __restrict__ X,
                  const __nv_bfloat16* __restrict__ W2T_hi,
                  const __nv_bfloat16* __restrict__ W2T_lo,
                  const float* __restrict__ b2,
                  const float* __restrict__ RES,
                  const __nv_bfloat16* __restrict__ WpT_hi,
                  const __nv_bfloat16* __restrict__ WpT_lo,
                  const float* __restrict__ bp,
                  float* __restrict__ OUT,
                  int nrows)
{
    constexpr int BM = 64, K = 128, N = 128, NP = 32;
    constexpr int SK = K + 8;
    constexpr int KS = K / 16;
    constexpr int WM1 = 2, MT1 = 2, WN1 = 32, NT1 = 4;
    constexpr int WN2 = 16, NT2 = 2;

    extern __shared__ __nv_bfloat16 smem[];
    __nv_bfloat16* Ah = smem;
    __nv_bfloat16* Al = Ah + BM * SK;
    __nv_bfloat16* Bh = Al + BM * SK;
    __nv_bfloat16* Bl = Bh + (size_t)N * SK;

    const int t = threadIdx.x;
    const int lane = t & 31;
    const int wid = t >> 5;
    const int row0 = blockIdx.x * BM;
    const int wm1 = wid % WM1, wn1 = wid / WM1;

    for (int i = t; i < N * K / 8; i += 256) {
        int n = (i * 8) / K;
        int k = (i * 8) % K;
        *reinterpret_cast<uint4*>(&Bh[n * SK + k]) = __ldg(reinterpret_cast<const uint4*>(W2T_hi) + i);
        *reinterpret_cast<uint4*>(&Bl[n * SK + k]) = __ldg(reinterpret_cast<const uint4*>(W2T_lo) + i);
    }
    for (int i = t; i < BM * K / 4; i += 256) {
        int row = (i * 4) / K;
        int col = (i * 4) % K;
        float4 v = make_float4(0.f, 0.f, 0.f, 0.f);
        int gr = row0 + row;
        if (gr < nrows)
            v = __ldg(reinterpret_cast<const float4*>(X + (size_t)gr * K) + (col >> 2));
        __nv_bfloat16 h0, h1, h2, h3, l0, l1, l2, l3;
        split2(v.x, h0, l0); split2(v.y, h1, l1);
        split2(v.z, h2, l2); split2(v.w, h3, l3);
        int o = row * SK + col;
        *reinterpret_cast<uint32_t*>(&Ah[o])     = pack_bf2(h0, h1);
        *reinterpret_cast<uint32_t*>(&Ah[o + 2]) = pack_bf2(h2, h3);
        *reinterpret_cast<uint32_t*>(&Al[o])     = pack_bf2(l0, l1);
        *reinterpret_cast<uint32_t*>(&Al[o + 2]) = pack_bf2(l2, l3);
    }
    __syncthreads();

    float acc[MT1][NT1][4] = {};
    for (int ks = 0; ks < KS; ks++) {
        const int k0 = ks * 16;
        const int tt = lane >> 3;
        const int tr = lane & 7;

        uint32_t a[MT1][2][4];
#pragma unroll
        for (int mt = 0; mt < MT1; mt++) {
            int r = wm1 * 32 + mt * 16 + (tt & 1) * 8 + tr;
            int c = k0 + (tt >> 1) * 8;
            LDMATRIX_X4(a[mt][0][0], a[mt][0][1], a[mt][0][2], a[mt][0][3],
                        smem_u32(&Ah[r * SK + c]));
            LDMATRIX_X4(a[mt][1][0], a[mt][1][1], a[mt][1][2], a[mt][1][3],
                        smem_u32(&Al[r * SK + c]));
        }
        uint32_t b[NT1][2][2];
#pragma unroll
        for (int p = 0; p < NT1 / 2; p++) {
            int n = wn1 * WN1 + p * 16 + (tt >> 1) * 8 + tr;
            int c = k0 + (tt & 1) * 8;
            uint32_t r0, r1, r2, r3;
            LDMATRIX_X4(r0, r1, r2, r3, smem_u32(&Bh[n * SK + c]));
            b[2*p][0][0] = r0; b[2*p][0][1] = r1;
            b[2*p+1][0][0] = r2; b[2*p+1][0][1] = r3;
            LDMATRIX_X4(r0, r1, r2, r3, smem_u32(&Bl[n * SK + c]));
            b[2*p][1][0] = r0; b[2*p][1][1] = r1;
            b[2*p+1][1][0] = r2; b[2*p+1][1][1] = r3;
        }
#pragma unroll
        for (int mt = 0; mt < MT1; mt++)
#pragma unroll
            for (int nt = 0; nt < NT1; nt++)
                mma_bf16(acc[mt][nt], a[mt][0], b[nt][0]);
#pragma unroll
        for (int mt = 0; mt < MT1; mt++)
#pragma unroll
            for (int nt = 0; nt < NT1; nt++)
                mma_bf16(acc[mt][nt], a[mt][0], b[nt][1]);
#pragma unroll
        for (int mt = 0; mt < MT1; mt++)
#pragma unroll
            for (int nt = 0; nt < NT1; nt++)
                mma_bf16(acc[mt][nt], a[mt][1], b[nt][0]);
    }
    __syncthreads();

#pragma unroll
    for (int mt = 0; mt < MT1; mt++) {
        int lr_lo = wm1 * 32 + mt * 16 + (lane >> 2);
        int lr_hi = lr_lo + 8;
#pragma unroll
        for (int nt = 0; nt < NT1; nt++) {
            int col = wn1 * WN1 + nt * 8 + (lane & 3) * 2;
            float bi0 = __ldg(&b2[col]);
            float bi1 = __ldg(&b2[col + 1]);
            {
                int gr = row0 + lr_lo;
                float o0 = fmaxf(acc[mt][nt][0] + bi0, 0.f);
                float o1 = fmaxf(acc[mt][nt][1] + bi1, 0.f);
                if (gr < nrows) {
                    float2 rr = __ldg(reinterpret_cast<const float2*>(RES + (size_t)gr * N + col));
                    o0 += rr.x; o1 += rr.y;
                }
                __nv_bfloat16 h0, h1, l0, l1;
                split2(o0, h0, l0); split2(o1, h1, l1);
                int o = lr_lo * SK + col;
                *reinterpret_cast<uint32_t*>(&Ah[o]) = pack_bf2(h0, h1);
                *reinterpret_cast<uint32_t*>(&Al[o]) = pack_bf2(l0, l1);
            }
            {
                int gr = row0 + lr_hi;
                float o0 = fmaxf(acc[mt][nt][2] + bi0, 0.f);
                float o1 = fmaxf(acc[mt][nt][3] + bi1, 0.f);
                if (gr < nrows) {
                    float2 rr = __ldg(reinterpret_cast<const float2*>(RES + (size_t)gr * N + col));
                    o0 += rr.x; o1 += rr.y;
                }
                __nv_bfloat16 h0, h1, l0, l1;
                split2(o0, h0, l0); split2(o1, h1, l1);
                int o = lr_hi * SK + col;
                *reinterpret_cast<uint32_t*>(&Ah[o]) = pack_bf2(h0, h1);
                *reinterpret_cast<uint32_t*>(&Al[o]) = pack_bf2(l0, l1);
            }
        }
    }

    for (int i = t; i < NP * K / 8; i += 256) {
        int n = (i * 8) / K;
        int k = (i * 8) % K;
        *reinterpret_cast<uint4*>(&Bh[n * SK + k]) = __ldg(reinterpret_cast<const uint4*>(WpT_hi) + i);
        *reinterpret_cast<uint4*>(&Bl[n * SK + k]) = __ldg(reinterpret_cast<const uint4*>(WpT_lo) + i);
    }
    __syncthreads();

    const int wm2 = wid % 4, wn2 = wid / 4;
    float acc2[NT2][4] = {};
    for (int ks = 0; ks < KS; ks++) {
        const int k0 = ks * 16;
        const int tt = lane >> 3;
        const int tr = lane & 7;

        uint32_t a[2][4];
        {
            int r = wm2 * 16 + (tt & 1) * 8 + tr;
            int c = k0 + (tt >> 1) * 8;
            LDMATRIX_X4(a[0][0], a[0][1], a[0][2], a[0][3], smem_u32(&Ah[r * SK + c]));
            LDMATRIX_X4(a[1][0], a[1][1], a[1][2], a[1][3], smem_u32(&Al[r * SK + c]));
        }
        uint32_t b[NT2][2][2];
        {
            int n = wn2 * WN2 + (tt >> 1) * 8 + tr;
            int c = k0 + (tt & 1) * 8;
            uint32_t r0, r1, r2, r3;
            LDMATRIX_X4(r0, r1, r2, r3, smem_u32(&Bh[n * SK + c]));
            b[0][0][0] = r0; b[0][0][1] = r1;
            b[1][0][0] = r2; b[1][0][1] = r3;
            LDMATRIX_X4(r0, r1, r2, r3, smem_u32(&Bl[n * SK + c]));
            b[0][1][0] = r0; b[0][1][1] = r1;
            b[1][1][0] = r2; b[1][1][1] = r3;
        }
#pragma unroll
        for (int nt = 0; nt < NT2; nt++) mma_bf16(acc2[nt], a[0], b[nt][0]);
#pragma unroll
        for (int nt = 0; nt < NT2; nt++) mma_bf16(acc2[nt], a[0], b[nt][1]);
#pragma unroll
        for (int nt = 0; nt < NT2; nt++) mma_bf16(acc2[nt], a[1], b[nt][0]);
    }

    {
        int r_lo = row0 + wm2 * 16 + (lane >> 2);
        int r_hi = r_lo + 8;
#pragma unroll
        for (int nt = 0; nt < NT2; nt++) {
            int col = wn2 * WN2 + nt * 8 + (lane & 3) * 2;
            float bi0 = __ldg(&bp[col]);
            float bi1 = __ldg(&bp[col + 1]);
            if (r_lo < nrows)
                *reinterpret_cast<float2*>(OUT + (size_t)r_lo * NP + col) =
                    make_float2(acc2[nt][0] + bi0, acc2[nt][1] + bi1);
            if (r_hi < nrows)
                *reinterpret_cast<float2*>(OUT + (size_t)r_hi * NP + col) =
                    make_float2(acc2[nt][2] + bi0, acc2[nt][3] + bi1);
        }
    }
}

// ===================== Launch ====================
extern "C" void kernel_launch(void* const* d_in, const int* in_sizes, int n_in,
                              void* d_out, int out_size)
{
    const float* x  = (const float*)d_in[0];
    const int*   ei = (const int*)d_in[1];
    const float* W0 = (const float*)d_in[2];
    const float* b0 = (const float*)d_in[3];
    const float* W1 = (const float*)d_in[4];
    const float* b1 = (const float*)d_in[5];
    const float* W2 = (const float*)d_in[6];
    const float* b2 = (const float*)d_in[7];
    const float* Wp = (const float*)d_in[8];
    const float* bp = (const float*)d_in[9];
    float* out = (float*)d_out;

    const int n_nodes = in_sizes[0] / 64;
    const int n_edges = in_sizes[1] / 2;
    const int nblocks = (n_nodes + 1023) / 1024;

    float *sum, *h0, *h1;
    __half *xh, *h0h, *h1h;
    int *row, *cur, *csr, *blk;
    __nv_bfloat16 *wthi, *wtlo;
    cudaGetSymbolAddress((void**)&sum,  g_sum);
    cudaGetSymbolAddress((void**)&h0,   g_h0);
    cudaGetSymbolAddress((void**)&h1,   g_h1);
    cudaGetSymbolAddress((void**)&xh,   g_xh);
    cudaGetSymbolAddress((void**)&h0h,  g_h0h);
    cudaGetSymbolAddress((void**)&h1h,  g_h1h);
    cudaGetSymbolAddress((void**)&row,  g_row);
    cudaGetSymbolAddress((void**)&cur,  g_cur);
    cudaGetSymbolAddress((void**)&csr,  g_csr);
    cudaGetSymbolAddress((void**)&blk,  g_blk);
    cudaGetSymbolAddress((void**)&wthi, g_wthi);
    cudaGetSymbolAddress((void**)&wtlo, g_wtlo);

    const int eb = (n_edges + 255) / 256;
    const int cur_blocks = (n_nodes + 255) / 256;
    const int xh_blocks  = (n_nodes * 16 + 255) / 256;
    const int prep_blocks = WT_BLOCKS + cur_blocks + xh_blocks;
    const int pull128_blocks = (n_nodes + 7) / 8;
    const int pull64_blocks  = (n_nodes + 15) / 16;
    const int gemm_blocks    = (n_nodes + 63) / 64;

    const int smem_l0 = (2 * 64 * 72  + 2 * 128 * 72)  * 2;  // 55296
    const int smem_l  = (2 * 64 * 136 + 2 * 128 * 136) * 2;  // 104448
    cudaFuncSetAttribute(gemm_mma<64, 128, 2, true, false>,
                         cudaFuncAttributeMaxDynamicSharedMemorySize, smem_l0);
    cudaFuncSetAttribute(gemm_mma<128, 128, 2, true, true>,
                         cudaFuncAttributeMaxDynamicSharedMemorySize, smem_l);
    cudaFuncSetAttribute(gemm_l2_proj,
                         cudaFuncAttributeMaxDynamicSharedMemorySize, smem_l);

    // ---- Prologue ----
    prep_kernel<<<prep_blocks, 256>>>(W0, W1, W2, Wp, x, xh, wthi, wtlo, cur,
                                      n_nodes, cur_blocks);
    count_kernel<<<eb, 256>>>(ei, cur, n_edges);
    scan_block<<<nblocks, 1024>>>(cur, row, blk, n_nodes);
    scan_sums<<<1, 64>>>(blk, row, nblocks, n_nodes);
    scan_add<<<nblocks, 1024>>>(row, blk, cur, n_nodes);
    fill_kernel<<<eb, 256>>>(ei, cur, csr, n_edges);

    // ---- Layer 0 ----
    pull64_kernel<<<pull64_blocks, 256>>>(x, xh, row, csr, sum, n_nodes);
    gemm_mma<64, 128, 2, true, false>
        <<<gemm_blocks, 256, smem_l0>>>(sum, wthi + WT0_OFF, wtlo + WT0_OFF, b0,
                                        nullptr, h0, h0h, n_nodes);

    // ---- Layer 1 ----
    pull128_kernel<<<pull128_blocks, 256>>>(h0, h0h, row, csr, sum, n_nodes);
    gemm_mma<128, 128, 2, true, true>
        <<<gemm_blocks, 256, smem_l>>>(sum, wthi + WT1_OFF, wtlo + WT1_OFF, b1,
                                       h0, h1, h1h, n_nodes);

    // ---- Layer 2 + projection (fused) ----
    pull128_kernel<<<pull128_blocks, 256>>>(h1, h1h, row, csr, sum, n_nodes);
    gemm_l2_proj<<<gemm_blocks, 256, smem_l>>>(sum, wthi + WT2_OFF, wtlo + WT2_OFF, b2, h1,
                                               wthi + WTP_OFF, wtlo + WTP_OFF, bp, out, n_nodes);
}

// round 14
// speedup vs baseline: 1.0323x; 1.0323x over previous
#include <cuda_runtime.h>
#include <cuda_bf16.h>
#include <cstdint>

// ---------------------------------------------------------------------------
// EigenGIN: 3x GINConv(sum-agg + Linear + ReLU, residual) + projection.
// CSR pull kernels (fp32, unroll-4 gather for MLP) + BM=64 mma.sync GEMMs
// (bf16-pair split), pre-transposed weights, hierarchical scan, projection
// fused into layer-2 GEMM.
// ---------------------------------------------------------------------------

#define MAX_NODES 50000
#define MAX_EDGES 800000
#define SCAN_BLOCKS ((MAX_NODES + 1023) / 1024)

__device__ float g_sum[MAX_NODES * 128];
__device__ float g_h0 [MAX_NODES * 128];
__device__ float g_h1 [MAX_NODES * 128];

__device__ int g_row[MAX_NODES + 1];
__device__ int g_cur[MAX_NODES];
__device__ int g_csr[MAX_EDGES];
__device__ int g_blk[SCAN_BLOCKS];

// WT buffers (bf16 hi/lo, [N][K] layout)
#define WT0_OFF 0
#define WT1_OFF 8192
#define WT2_OFF 24576
#define WTP_OFF 40960
#define WT_TOTAL 45056
#define WT_BLOCKS ((WT_TOTAL + 255) / 256)
__device__ __nv_bfloat16 g_wthi[WT_TOTAL];
__device__ __nv_bfloat16 g_wtlo[WT_TOTAL];

// ===================== helpers ====================
__device__ __forceinline__ uint32_t smem_u32(const void* p) {
    uint32_t a;
    asm("{ .reg .u64 t; cvta.to.shared.u64 t, %1; cvt.u32.u64 %0, t; }"
        : "=r"(a) : "l"(p));
    return a;
}

#define LDMATRIX_X4(R0, R1, R2, R3, ADDR) \
    asm volatile("ldmatrix.sync.aligned.m8n8.x4.shared.b16 {%0,%1,%2,%3}, [%4];" \
                 : "=r"(R0), "=r"(R1), "=r"(R2), "=r"(R3) : "r"(ADDR))

__device__ __forceinline__ void mma_bf16(float* c, const uint32_t* a, const uint32_t* b) {
    asm volatile(
        "mma.sync.aligned.m16n8k16.row.col.f32.bf16.bf16.f32 "
        "{%0,%1,%2,%3}, {%4,%5,%6,%7}, {%8,%9}, {%0,%1,%2,%3};"
        : "+f"(c[0]), "+f"(c[1]), "+f"(c[2]), "+f"(c[3])
        : "r"(a[0]), "r"(a[1]), "r"(a[2]), "r"(a[3]), "r"(b[0]), "r"(b[1]));
}

__device__ __forceinline__ uint32_t pack_bf2(__nv_bfloat16 a, __nv_bfloat16 b) {
    return (uint32_t)__bfloat16_as_ushort(a) | ((uint32_t)__bfloat16_as_ushort(b) << 16);
}
__device__ __forceinline__ void split2(float f, __nv_bfloat16& h, __nv_bfloat16& l) {
    h = __float2bfloat16(f);
    l = __float2bfloat16(f - __bfloat162float(h));
}

// ===================== Prologue kernels ====================
__global__ void prep_kernel(const float* __restrict__ W0, const float* __restrict__ W1,
                            const float* __restrict__ W2, const float* __restrict__ Wp,
                            __nv_bfloat16* __restrict__ hi, __nv_bfloat16* __restrict__ lo,
                            int* __restrict__ cur, int n_nodes)
{
    int b = blockIdx.x;
    if (b < WT_BLOCKS) {
        int i = b * 256 + threadIdx.x;
        if (i >= WT_TOTAL) return;
        const float* W; int K, N, off, local;
        if (i < 8192)       { W = W0; K = 64;  N = 128; off = WT0_OFF; local = i; }
        else if (i < 24576) { W = W1; K = 128; N = 128; off = WT1_OFF; local = i - 8192; }
        else if (i < 40960) { W = W2; K = 128; N = 128; off = WT2_OFF; local = i - 24576; }
        else                { W = Wp; K = 128; N = 32;  off = WTP_OFF; local = i - 40960; }
        int k = local / N, n = local % N;
        __nv_bfloat16 h, l;
        split2(__ldg(&W[local]), h, l);
        hi[off + n * K + k] = h;
        lo[off + n * K + k] = l;
    } else {
        int i = (b - WT_BLOCKS) * 256 + threadIdx.x;
        if (i < n_nodes) cur[i] = 0;
    }
}

__global__ void count_kernel(const int* __restrict__ ei, int* __restrict__ counts,
                             int n_edges)
{
    int e = blockIdx.x * blockDim.x + threadIdx.x;
    if (e < n_edges) atomicAdd(&counts[__ldg(&ei[n_edges + e])], 1);
}

__global__ void scan_block(const int* __restrict__ counts, int* __restrict__ excl,
                           int* __restrict__ blk_sums, int n)
{
    __shared__ int sd[1024];
    int tid = threadIdx.x;
    int i = blockIdx.x * 1024 + tid;
    int v = (i < n) ? counts[i] : 0;
    sd[tid] = v;
    __syncthreads();
#pragma unroll
    for (int off = 1; off < 1024; off <<= 1) {
        int tv = (tid >= off) ? sd[tid - off] : 0;
        __syncthreads();
        sd[tid] += tv;
        __syncthreads();
    }
    if (i < n) excl[i] = sd[tid] - v;
    if (tid == 1023) blk_sums[blockIdx.x] = sd[1023];
}

__global__ void scan_sums(int* __restrict__ blk_sums, int* __restrict__ row_start,
                          int nblocks, int n)
{
    __shared__ int sd[64];
    int tid = threadIdx.x;
    int v = (tid < nblocks) ? blk_sums[tid] : 0;
    sd[tid] = v;
    __syncthreads();
#pragma unroll
    for (int off = 1; off < 64; off <<= 1) {
        int tv = (tid >= off) ? sd[tid - off] : 0;
        __syncthreads();
        sd[tid] += tv;
        __syncthreads();
    }
    if (tid < nblocks) blk_sums[tid] = sd[tid] - v;
    if (tid == 63) row_start[n] = sd[63];
}

__global__ void scan_add(int* __restrict__ excl, const int* __restrict__ blk_sums,
                         int* __restrict__ cursor, int n)
{
    int i = blockIdx.x * 1024 + threadIdx.x;
    if (i < n) {
        int v = excl[i] + blk_sums[blockIdx.x];
        excl[i] = v;
        cursor[i] = v;
    }
}

__global__ void fill_kernel(const int* __restrict__ ei, int* __restrict__ cursor,
                            int* __restrict__ csr_src, int n_edges)
{
    int e = blockIdx.x * blockDim.x + threadIdx.x;
    if (e < n_edges) {
        int d = __ldg(&ei[n_edges + e]);
        int s = __ldg(&ei[e]);
        int pos = atomicAdd(&cursor[d], 1);
        csr_src[pos] = s;
    }
}

// ===================== Pull aggregation (unroll-4 gather) ==================
__global__ void pull128_kernel(const float* __restrict__ feat,
                               const int* __restrict__ row_start,
                               const int* __restrict__ csr_src,
                               float* __restrict__ out, int n_nodes)
{
    int node = (blockIdx.x * blockDim.x + threadIdx.x) >> 5;
    int lane = threadIdx.x & 31;
    if (node >= n_nodes) return;
    int e0 = __ldg(&row_start[node]);
    int e1 = __ldg(&row_start[node + 1]);
    float4 acc = __ldg(reinterpret_cast<const float4*>(feat + (size_t)node * 128) + lane);
    int e = e0;
    for (; e + 3 < e1; e += 4) {
        int s0 = __ldg(&csr_src[e]);
        int s1 = __ldg(&csr_src[e + 1]);
        int s2 = __ldg(&csr_src[e + 2]);
        int s3 = __ldg(&csr_src[e + 3]);
        float4 v0 = __ldg(reinterpret_cast<const float4*>(feat + (size_t)s0 * 128) + lane);
        float4 v1 = __ldg(reinterpret_cast<const float4*>(feat + (size_t)s1 * 128) + lane);
        float4 v2 = __ldg(reinterpret_cast<const float4*>(feat + (size_t)s2 * 128) + lane);
        float4 v3 = __ldg(reinterpret_cast<const float4*>(feat + (size_t)s3 * 128) + lane);
        acc.x += (v0.x + v1.x) + (v2.x + v3.x);
        acc.y += (v0.y + v1.y) + (v2.y + v3.y);
        acc.z += (v0.z + v1.z) + (v2.z + v3.z);
        acc.w += (v0.w + v1.w) + (v2.w + v3.w);
    }
    for (; e < e1; e++) {
        int s = __ldg(&csr_src[e]);
        float4 v = __ldg(reinterpret_cast<const float4*>(feat + (size_t)s * 128) + lane);
        acc.x += v.x; acc.y += v.y; acc.z += v.z; acc.w += v.w;
    }
    *reinterpret_cast<float4*>(out + (size_t)node * 128 + lane * 4) = acc;
}

__global__ void pull64_kernel(const float* __restrict__ feat,
                              const int* __restrict__ row_start,
                              const int* __restrict__ csr_src,
                              float* __restrict__ out, int n_nodes)
{
    int gw   = (blockIdx.x * blockDim.x + threadIdx.x) >> 5;
    int lane = threadIdx.x & 31;
    int node = gw * 2 + (lane >> 4);
    int sub  = lane & 15;
    if (node >= n_nodes) return;
    int e0 = __ldg(&row_start[node]);
    int e1 = __ldg(&row_start[node + 1]);
    float4 acc = __ldg(reinterpret_cast<const float4*>(feat + (size_t)node * 64) + sub);
    int e = e0;
    for (; e + 3 < e1; e += 4) {
        int s0 = __ldg(&csr_src[e]);
        int s1 = __ldg(&csr_src[e + 1]);
        int s2 = __ldg(&csr_src[e + 2]);
        int s3 = __ldg(&csr_src[e + 3]);
        float4 v0 = __ldg(reinterpret_cast<const float4*>(feat + (size_t)s0 * 64) + sub);
        float4 v1 = __ldg(reinterpret_cast<const float4*>(feat + (size_t)s1 * 64) + sub);
        float4 v2 = __ldg(reinterpret_cast<const float4*>(feat + (size_t)s2 * 64) + sub);
        float4 v3 = __ldg(reinterpret_cast<const float4*>(feat + (size_t)s3 * 64) + sub);
        acc.x += (v0.x + v1.x) + (v2.x + v3.x);
        acc.y += (v0.y + v1.y) + (v2.y + v3.y);
        acc.z += (v0.z + v1.z) + (v2.z + v3.z);
        acc.w += (v0.w + v1.w) + (v2.w + v3.w);
    }
    for (; e < e1; e++) {
        int s = __ldg(&csr_src[e]);
        float4 v = __ldg(reinterpret_cast<const float4*>(feat + (size_t)s * 64) + sub);
        acc.x += v.x; acc.y += v.y; acc.z += v.z; acc.w += v.w;
    }
    *reinterpret_cast<float4*>(out + (size_t)node * 64 + sub * 4) = acc;
}

// ===================== mma.sync GEMM (BM=64) ====================
template <int K, int N, int WM, bool RELU, bool RESID>
__global__ __launch_bounds__(256)
void gemm_mma(const float* __restrict__ X,
              const __nv_bfloat16* __restrict__ WT_hi,
              const __nv_bfloat16* __restrict__ WT_lo,
              const float* __restrict__ Bv,
              const float* __restrict__ RES,
              float* __restrict__ OUT,
              int nrows)
{
    constexpr int BM = 64;
    constexpr int SK = K + 8;
    constexpr int WNW = 8 / WM;
    constexpr int MT = BM / WM / 16;
    constexpr int WN = N / WNW;
    constexpr int NT = WN / 8;
    constexpr int KS = K / 16;

    extern __shared__ __nv_bfloat16 smem[];
    __nv_bfloat16* Ah = smem;
    __nv_bfloat16* Al = Ah + BM * SK;
    __nv_bfloat16* Bh = Al + BM * SK;
    __nv_bfloat16* Bl = Bh + (size_t)N * SK;

    const int t = threadIdx.x;
    const int lane = t & 31;
    const int wid = t >> 5;
    const int wm = wid % WM;
    const int wn = wid / WM;
    const int row0 = blockIdx.x * BM;

    for (int i = t; i < N * K / 8; i += 256) {
        int n = (i * 8) / K;
        int k = (i * 8) % K;
        uint4 vh = __ldg(reinterpret_cast<const uint4*>(WT_hi) + i);
        uint4 vl = __ldg(reinterpret_cast<const uint4*>(WT_lo) + i);
        *reinterpret_cast<uint4*>(&Bh[n * SK + k]) = vh;
        *reinterpret_cast<uint4*>(&Bl[n * SK + k]) = vl;
    }

    for (int i = t; i < BM * K / 4; i += 256) {
        int row = (i * 4) / K;
        int col = (i * 4) % K;
        float4 v = make_float4(0.f, 0.f, 0.f, 0.f);
        int gr = row0 + row;
        if (gr < nrows)
            v = __ldg(reinterpret_cast<const float4*>(X + (size_t)gr * K) + (col >> 2));
        __nv_bfloat16 h0, h1, h2, h3, l0, l1, l2, l3;
        split2(v.x, h0, l0); split2(v.y, h1, l1);
        split2(v.z, h2, l2); split2(v.w, h3, l3);
        int o = row * SK + col;
        *reinterpret_cast<uint32_t*>(&Ah[o])     = pack_bf2(h0, h1);
        *reinterpret_cast<uint32_t*>(&Ah[o + 2]) = pack_bf2(h2, h3);
        *reinterpret_cast<uint32_t*>(&Al[o])     = pack_bf2(l0, l1);
        *reinterpret_cast<uint32_t*>(&Al[o + 2]) = pack_bf2(l2, l3);
    }
    __syncthreads();

    float acc[MT][NT][4] = {};
    for (int ks = 0; ks < KS; ks++) {
        const int k0 = ks * 16;
        const int tt = lane >> 3;
        const int tr = lane & 7;

        uint32_t a[MT][2][4];
#pragma unroll
        for (int mt = 0; mt < MT; mt++) {
            int r = wm * (MT * 16) + mt * 16 + (tt & 1) * 8 + tr;
            int c = k0 + (tt >> 1) * 8;
            LDMATRIX_X4(a[mt][0][0], a[mt][0][1], a[mt][0][2], a[mt][0][3],
                        smem_u32(&Ah[r * SK + c]));
            LDMATRIX_X4(a[mt][1][0], a[mt][1][1], a[mt][1][2], a[mt][1][3],
                        smem_u32(&Al[r * SK + c]));
        }

        uint32_t b[NT][2][2];
#pragma unroll
        for (int p = 0; p < NT / 2; p++) {
            int n = wn * WN + p * 16 + (tt >> 1) * 8 + tr;
            int c = k0 + (tt & 1) * 8;
            uint32_t r0, r1, r2, r3;
            LDMATRIX_X4(r0, r1, r2, r3, smem_u32(&Bh[n * SK + c]));
            b[2*p][0][0] = r0; b[2*p][0][1] = r1;
            b[2*p+1][0][0] = r2; b[2*p+1][0][1] = r3;
            LDMATRIX_X4(r0, r1, r2, r3, smem_u32(&Bl[n * SK + c]));
            b[2*p][1][0] = r0; b[2*p][1][1] = r1;
            b[2*p+1][1][0] = r2; b[2*p+1][1][1] = r3;
        }

#pragma unroll
        for (int mt = 0; mt < MT; mt++)
#pragma unroll
            for (int nt = 0; nt < NT; nt++)
                mma_bf16(acc[mt][nt], a[mt][0], b[nt][0]);
#pragma unroll
        for (int mt = 0; mt < MT; mt++)
#pragma unroll
            for (int nt = 0; nt < NT; nt++)
                mma_bf16(acc[mt][nt], a[mt][0], b[nt][1]);
#pragma unroll
        for (int mt = 0; mt < MT; mt++)
#pragma unroll
            for (int nt = 0; nt < NT; nt++)
                mma_bf16(acc[mt][nt], a[mt][1], b[nt][0]);
    }

#pragma unroll
    for (int mt = 0; mt < MT; mt++) {
        int r_lo = row0 + wm * (MT * 16) + mt * 16 + (lane >> 2);
        int r_hi = r_lo + 8;
#pragma unroll
        for (int nt = 0; nt < NT; nt++) {
            int col = wn * WN + nt * 8 + (lane & 3) * 2;
            float bi0 = __ldg(&Bv[col]);
            float bi1 = __ldg(&Bv[col + 1]);
            if (r_lo < nrows) {
                float o0 = acc[mt][nt][0] + bi0;
                float o1 = acc[mt][nt][1] + bi1;
                if (RELU) { o0 = fmaxf(o0, 0.f); o1 = fmaxf(o1, 0.f); }
                if (RESID) {
                    float2 rr = __ldg(reinterpret_cast<const float2*>(RES + (size_t)r_lo * N + col));
                    o0 += rr.x; o1 += rr.y;
                }
                *reinterpret_cast<float2*>(OUT + (size_t)r_lo * N + col) = make_float2(o0, o1);
            }
            if (r_hi < nrows) {
                float o0 = acc[mt][nt][2] + bi0;
                float o1 = acc[mt][nt][3] + bi1;
                if (RELU) { o0 = fmaxf(o0, 0.f); o1 = fmaxf(o1, 0.f); }
                if (RESID) {
                    float2 rr = __ldg(reinterpret_cast<const float2*>(RES + (size_t)r_hi * N + col));
                    o0 += rr.x; o1 += rr.y;
                }
                *reinterpret_cast<float2*>(OUT + (size_t)r_hi * N + col) = make_float2(o0, o1);
            }
        }
    }
}

// ===================== Fused layer-2 GEMM + projection ====================
__global__ __launch_bounds__(256)
void gemm_l2_proj(const float* __restrict__ X,
                  const __nv_bfloat16* __restrict__ W2T_hi,
                  const __nv_bfloat16* __restrict__ W2T_lo,
                  const float* __restrict__ b2,
                  const float* __restrict__ RES,
                  const __nv_bfloat16* __restrict__ WpT_hi,
                  const __nv_bfloat16* __restrict__ WpT_lo,
                  const float* __restrict__ bp,
                  float* __restrict__ OUT,
                  int nrows)
{
    constexpr int BM = 64, K = 128, N = 128, NP = 32;
    constexpr int SK = K + 8;
    constexpr int KS = K / 16;
    constexpr int WM1 = 2, MT1 = 2, WN1 = 32, NT1 = 4;
    constexpr int WN2 = 16, NT2 = 2;

    extern __shared__ __nv_bfloat16 smem[];
    __nv_bfloat16* Ah = smem;
    __nv_bfloat16* Al = Ah + BM * SK;
    __nv_bfloat16* Bh = Al + BM * SK;
    __nv_bfloat16* Bl = Bh + (size_t)N * SK;

    const int t = threadIdx.x;
    const int lane = t & 31;
    const int wid = t >> 5;
    const int row0 = blockIdx.x * BM;
    const int wm1 = wid % WM1, wn1 = wid / WM1;

    for (int i = t; i < N * K / 8; i += 256) {
        int n = (i * 8) / K;
        int k = (i * 8) % K;
        *reinterpret_cast<uint4*>(&Bh[n * SK + k]) = __ldg(reinterpret_cast<const uint4*>(W2T_hi) + i);
        *reinterpret_cast<uint4*>(&Bl[n * SK + k]) = __ldg(reinterpret_cast<const uint4*>(W2T_lo) + i);
    }
    for (int i = t; i < BM * K / 4; i += 256) {
        int row = (i * 4) / K;
        int col = (i * 4) % K;
        float4 v = make_float4(0.f, 0.f, 0.f, 0.f);
        int gr = row0 + row;
        if (gr < nrows)
            v = __ldg(reinterpret_cast<const float4*>(X + (size_t)gr * K) + (col >> 2));
        __nv_bfloat16 h0, h1, h2, h3, l0, l1, l2, l3;
        split2(v.x, h0, l0); split2(v.y, h1, l1);
        split2(v.z, h2, l2); split2(v.w, h3, l3);
        int o = row * SK + col;
        *reinterpret_cast<uint32_t*>(&Ah[o])     = pack_bf2(h0, h1);
        *reinterpret_cast<uint32_t*>(&Ah[o + 2]) = pack_bf2(h2, h3);
        *reinterpret_cast<uint32_t*>(&Al[o])     = pack_bf2(l0, l1);
        *reinterpret_cast<uint32_t*>(&Al[o + 2]) = pack_bf2(l2, l3);
    }
    __syncthreads();

    float acc[MT1][NT1][4] = {};
    for (int ks = 0; ks < KS; ks++) {
        const int k0 = ks * 16;
        const int tt = lane >> 3;
        const int tr = lane & 7;

        uint32_t a[MT1][2][4];
#pragma unroll
        for (int mt = 0; mt < MT1; mt++) {
            int r = wm1 * 32 + mt * 16 + (tt & 1) * 8 + tr;
            int c = k0 + (tt >> 1) * 8;
            LDMATRIX_X4(a[mt][0][0], a[mt][0][1], a[mt][0][2], a[mt][0][3],
                        smem_u32(&Ah[r * SK + c]));
            LDMATRIX_X4(a[mt][1][0], a[mt][1][1], a[mt][1][2], a[mt][1][3],
                        smem_u32(&Al[r * SK + c]));
        }
        uint32_t b[NT1][2][2];
#pragma unroll
        for (int p = 0; p < NT1 / 2; p++) {
            int n = wn1 * WN1 + p * 16 + (tt >> 1) * 8 + tr;
            int c = k0 + (tt & 1) * 8;
            uint32_t r0, r1, r2, r3;
            LDMATRIX_X4(r0, r1, r2, r3, smem_u32(&Bh[n * SK + c]));
            b[2*p][0][0] = r0; b[2*p][0][1] = r1;
            b[2*p+1][0][0] = r2; b[2*p+1][0][1] = r3;
            LDMATRIX_X4(r0, r1, r2, r3, smem_u32(&Bl[n * SK + c]));
            b[2*p][1][0] = r0; b[2*p][1][1] = r1;
            b[2*p+1][1][0] = r2; b[2*p+1][1][1] = r3;
        }
#pragma unroll
        for (int mt = 0; mt < MT1; mt++)
#pragma unroll
            for (int nt = 0; nt < NT1; nt++)
                mma_bf16(acc[mt][nt], a[mt][0], b[nt][0]);
#pragma unroll
        for (int mt = 0; mt < MT1; mt++)
#pragma unroll
            for (int nt = 0; nt < NT1; nt++)
                mma_bf16(acc[mt][nt], a[mt][0], b[nt][1]);
#pragma unroll
        for (int mt = 0; mt < MT1; mt++)
#pragma unroll
            for (int nt = 0; nt < NT1; nt++)
                mma_bf16(acc[mt][nt], a[mt][1], b[nt][0]);
    }
    __syncthreads();

#pragma unroll
    for (int mt = 0; mt < MT1; mt++) {
        int lr_lo = wm1 * 32 + mt * 16 + (lane >> 2);
        int lr_hi = lr_lo + 8;
#pragma unroll
        for (int nt = 0; nt < NT1; nt++) {
            int col = wn1 * WN1 + nt * 8 + (lane & 3) * 2;
            float bi0 = __ldg(&b2[col]);
            float bi1 = __ldg(&b2[col + 1]);
            {
                int gr = row0 + lr_lo;
                float o0 = fmaxf(acc[mt][nt][0] + bi0, 0.f);
                float o1 = fmaxf(acc[mt][nt][1] + bi1, 0.f);
                if (gr < nrows) {
                    float2 rr = __ldg(reinterpret_cast<const float2*>(RES + (size_t)gr * N + col));
                    o0 += rr.x; o1 += rr.y;
                }
                __nv_bfloat16 h0, h1, l0, l1;
                split2(o0, h0, l0); split2(o1, h1, l1);
                int o = lr_lo * SK + col;
                *reinterpret_cast<uint32_t*>(&Ah[o]) = pack_bf2(h0, h1);
                *reinterpret_cast<uint32_t*>(&Al[o]) = pack_bf2(l0, l1);
            }
            {
                int gr = row0 + lr_hi;
                float o0 = fmaxf(acc[mt][nt][2] + bi0, 0.f);
                float o1 = fmaxf(acc[mt][nt][3] + bi1, 0.f);
                if (gr < nrows) {
                    float2 rr = __ldg(reinterpret_cast<const float2*>(RES + (size_t)gr * N + col));
                    o0 += rr.x; o1 += rr.y;
                }
                __nv_bfloat16 h0, h1, l0, l1;
                split2(o0, h0, l0); split2(o1, h1, l1);
                int o = lr_hi * SK + col;
                *reinterpret_cast<uint32_t*>(&Ah[o]) = pack_bf2(h0, h1);
                *reinterpret_cast<uint32_t*>(&Al[o]) = pack_bf2(l0, l1);
            }
        }
    }

    for (int i = t; i < NP * K / 8; i += 256) {
        int n = (i * 8) / K;
        int k = (i * 8) % K;
        *reinterpret_cast<uint4*>(&Bh[n * SK + k]) = __ldg(reinterpret_cast<const uint4*>(WpT_hi) + i);
        *reinterpret_cast<uint4*>(&Bl[n * SK + k]) = __ldg(reinterpret_cast<const uint4*>(WpT_lo) + i);
    }
    __syncthreads();

    const int wm2 = wid % 4, wn2 = wid / 4;
    float acc2[NT2][4] = {};
    for (int ks = 0; ks < KS; ks++) {
        const int k0 = ks * 16;
        const int tt = lane >> 3;
        const int tr = lane & 7;

        uint32_t a[2][4];
        {
            int r = wm2 * 16 + (tt & 1) * 8 + tr;
            int c = k0 + (tt >> 1) * 8;
            LDMATRIX_X4(a[0][0], a[0][1], a[0][2], a[0][3], smem_u32(&Ah[r * SK + c]));
            LDMATRIX_X4(a[1][0], a[1][1], a[1][2], a[1][3], smem_u32(&Al[r * SK + c]));
        }
        uint32_t b[NT2][2][2];
        {
            int n = wn2 * WN2 + (tt >> 1) * 8 + tr;
            int c = k0 + (tt & 1) * 8;
            uint32_t r0, r1, r2, r3;
            LDMATRIX_X4(r0, r1, r2, r3, smem_u32(&Bh[n * SK + c]));
            b[0][0][0] = r0; b[0][0][1] = r1;
            b[1][0][0] = r2; b[1][0][1] = r3;
            LDMATRIX_X4(r0, r1, r2, r3, smem_u32(&Bl[n * SK + c]));
            b[0][1][0] = r0; b[0][1][1] = r1;
            b[1][1][0] = r2; b[1][1][1] = r3;
        }
#pragma unroll
        for (int nt = 0; nt < NT2; nt++) mma_bf16(acc2[nt], a[0], b[nt][0]);
#pragma unroll
        for (int nt = 0; nt < NT2; nt++) mma_bf16(acc2[nt], a[0], b[nt][1]);
#pragma unroll
        for (int nt = 0; nt < NT2; nt++) mma_bf16(acc2[nt], a[1], b[nt][0]);
    }

    {
        int r_lo = row0 + wm2 * 16 + (lane >> 2);
        int r_hi = r_lo + 8;
#pragma unroll
        for (int nt = 0; nt < NT2; nt++) {
            int col = wn2 * WN2 + nt * 8 + (lane & 3) * 2;
            float bi0 = __ldg(&bp[col]);
            float bi1 = __ldg(&bp[col + 1]);
            if (r_lo < nrows)
                *reinterpret_cast<float2*>(OUT + (size_t)r_lo * NP + col) =
                    make_float2(acc2[nt][0] + bi0, acc2[nt][1] + bi1);
            if (r_hi < nrows)
                *reinterpret_cast<float2*>(OUT + (size_t)r_hi * NP + col) =
                    make_float2(acc2[nt][2] + bi0, acc2[nt][3] + bi1);
        }
    }
}

// ===================== Launch ====================
extern "C" void kernel_launch(void* const* d_in, const int* in_sizes, int n_in,
                              void* d_out, int out_size)
{
    const float* x  = (const float*)d_in[0];
    const int*   ei = (const int*)d_in[1];
    const float* W0 = (const float*)d_in[2];
    const float* b0 = (const float*)d_in[3];
    const float* W1 = (const float*)d_in[4];
    const float* b1 = (const float*)d_in[5];
    const float* W2 = (const float*)d_in[6];
    const float* b2 = (const float*)d_in[7];
    const float* Wp = (const float*)d_in[8];
    const float* bp = (const float*)d_in[9];
    float* out = (float*)d_out;

    const int n_nodes = in_sizes[0] / 64;
    const int n_edges = in_sizes[1] / 2;
    const int nblocks = (n_nodes + 1023) / 1024;

    float *sum, *h0, *h1;
    int *row, *cur, *csr, *blk;
    __nv_bfloat16 *wthi, *wtlo;
    cudaGetSymbolAddress((void**)&sum,  g_sum);
    cudaGetSymbolAddress((void**)&h0,   g_h0);
    cudaGetSymbolAddress((void**)&h1,   g_h1);
    cudaGetSymbolAddress((void**)&row,  g_row);
    cudaGetSymbolAddress((void**)&cur,  g_cur);
    cudaGetSymbolAddress((void**)&csr,  g_csr);
    cudaGetSymbolAddress((void**)&blk,  g_blk);
    cudaGetSymbolAddress((void**)&wthi, g_wthi);
    cudaGetSymbolAddress((void**)&wtlo, g_wtlo);

    const int eb = (n_edges + 255) / 256;
    const int prep_blocks = WT_BLOCKS + (n_nodes + 255) / 256;
    const int pull128_blocks = (n_nodes + 7) / 8;
    const int pull64_blocks  = (n_nodes + 15) / 16;
    const int gemm_blocks    = (n_nodes + 63) / 64;

    const int smem_l0 = (2 * 64 * 72  + 2 * 128 * 72)  * 2;  // 55296
    const int smem_l  = (2 * 64 * 136 + 2 * 128 * 136) * 2;  // 104448
    cudaFuncSetAttribute(gemm_mma<64, 128, 2, true, false>,
                         cudaFuncAttributeMaxDynamicSharedMemorySize, smem_l0);
    cudaFuncSetAttribute(gemm_mma<128, 128, 2, true, true>,
                         cudaFuncAttributeMaxDynamicSharedMemorySize, smem_l);
    cudaFuncSetAttribute(gemm_l2_proj,
                         cudaFuncAttributeMaxDynamicSharedMemorySize, smem_l);

    // ---- Prologue: prep (wtrans + zero cur) -> count -> scan(x3) -> fill ----
    prep_kernel<<<prep_blocks, 256>>>(W0, W1, W2, Wp, wthi, wtlo, cur, n_nodes);
    count_kernel<<<eb, 256>>>(ei, cur, n_edges);
    scan_block<<<nblocks, 1024>>>(cur, row, blk, n_nodes);
    scan_sums<<<1, 64>>>(blk, row, nblocks, n_nodes);
    scan_add<<<nblocks, 1024>>>(row, blk, cur, n_nodes);
    fill_kernel<<<eb, 256>>>(ei, cur, csr, n_edges);

    // ---- Layer 0 ----
    pull64_kernel<<<pull64_blocks, 256>>>(x, row, csr, sum, n_nodes);
    gemm_mma<64, 128, 2, true, false>
        <<<gemm_blocks, 256, smem_l0>>>(sum, wthi + WT0_OFF, wtlo + WT0_OFF, b0, nullptr, h0, n_nodes);

    // ---- Layer 1 ----
    pull128_kernel<<<pull128_blocks, 256>>>(h0, row, csr, sum, n_nodes);
    gemm_mma<128, 128, 2, true, true>
        <<<gemm_blocks, 256, smem_l>>>(sum, wthi + WT1_OFF, wtlo + WT1_OFF, b1, h0, h1, n_nodes);

    // ---- Layer 2 + projection (fused) ----
    pull128_kernel<<<pull128_blocks, 256>>>(h1, row, csr, sum, n_nodes);
    gemm_l2_proj<<<gemm_blocks, 256, smem_l>>>(sum, wthi + WT2_OFF, wtlo + WT2_OFF, b2, h1,
                                               wthi + WTP_OFF, wtlo + WTP_OFF, bp, out, n_nodes);
}

// round 15
// speedup vs baseline: 1.0424x; 1.0098x over previous
#include <cuda_runtime.h>
#include <cuda_bf16.h>
#include <cstdint>

// ---------------------------------------------------------------------------
// EigenGIN: 3x GINConv(sum-agg + Linear + ReLU, residual) + projection.
// CSR pull kernels + BM=64 mma.sync GEMMs (bf16-pair split), pre-transposed
// weights. Two-kernel scan (block offsets recomputed per-block in scan_add).
// Projection fused into layer-2 GEMM.
// ---------------------------------------------------------------------------

#define MAX_NODES 50000
#define MAX_EDGES 800000
#define SCAN_BLOCKS ((MAX_NODES + 1023) / 1024)

__device__ float g_sum[MAX_NODES * 128];
__device__ float g_h0 [MAX_NODES * 128];
__device__ float g_h1 [MAX_NODES * 128];

__device__ int g_row[MAX_NODES + 1];
__device__ int g_cur[MAX_NODES];
__device__ int g_csr[MAX_EDGES];
__device__ int g_blk[SCAN_BLOCKS];

// WT buffers (bf16 hi/lo, [N][K] layout)
#define WT0_OFF 0
#define WT1_OFF 8192
#define WT2_OFF 24576
#define WTP_OFF 40960
#define WT_TOTAL 45056
#define WT_BLOCKS ((WT_TOTAL + 255) / 256)
__device__ __nv_bfloat16 g_wthi[WT_TOTAL];
__device__ __nv_bfloat16 g_wtlo[WT_TOTAL];

// ===================== helpers ====================
__device__ __forceinline__ uint32_t smem_u32(const void* p) {
    uint32_t a;
    asm("{ .reg .u64 t; cvta.to.shared.u64 t, %1; cvt.u32.u64 %0, t; }"
        : "=r"(a) : "l"(p));
    return a;
}

#define LDMATRIX_X4(R0, R1, R2, R3, ADDR) \
    asm volatile("ldmatrix.sync.aligned.m8n8.x4.shared.b16 {%0,%1,%2,%3}, [%4];" \
                 : "=r"(R0), "=r"(R1), "=r"(R2), "=r"(R3) : "r"(ADDR))

__device__ __forceinline__ void mma_bf16(float* c, const uint32_t* a, const uint32_t* b) {
    asm volatile(
        "mma.sync.aligned.m16n8k16.row.col.f32.bf16.bf16.f32 "
        "{%0,%1,%2,%3}, {%4,%5,%6,%7}, {%8,%9}, {%0,%1,%2,%3};"
        : "+f"(c[0]), "+f"(c[1]), "+f"(c[2]), "+f"(c[3])
        : "r"(a[0]), "r"(a[1]), "r"(a[2]), "r"(a[3]), "r"(b[0]), "r"(b[1]));
}

__device__ __forceinline__ uint32_t pack_bf2(__nv_bfloat16 a, __nv_bfloat16 b) {
    return (uint32_t)__bfloat16_as_ushort(a) | ((uint32_t)__bfloat16_as_ushort(b) << 16);
}
__device__ __forceinline__ void split2(float f, __nv_bfloat16& h, __nv_bfloat16& l) {
    h = __float2bfloat16(f);
    l = __float2bfloat16(f - __bfloat162float(h));
}

// ===================== Prologue kernels ====================
__global__ void prep_kernel(const float* __restrict__ W0, const float* __restrict__ W1,
                            const float* __restrict__ W2, const float* __restrict__ Wp,
                            __nv_bfloat16* __restrict__ hi, __nv_bfloat16* __restrict__ lo,
                            int* __restrict__ cur, int n_nodes)
{
    int b = blockIdx.x;
    if (b < WT_BLOCKS) {
        int i = b * 256 + threadIdx.x;
        if (i >= WT_TOTAL) return;
        const float* W; int K, N, off, local;
        if (i < 8192)       { W = W0; K = 64;  N = 128; off = WT0_OFF; local = i; }
        else if (i < 24576) { W = W1; K = 128; N = 128; off = WT1_OFF; local = i - 8192; }
        else if (i < 40960) { W = W2; K = 128; N = 128; off = WT2_OFF; local = i - 24576; }
        else                { W = Wp; K = 128; N = 32;  off = WTP_OFF; local = i - 40960; }
        int k = local / N, n = local % N;
        __nv_bfloat16 h, l;
        split2(__ldg(&W[local]), h, l);
        hi[off + n * K + k] = h;
        lo[off + n * K + k] = l;
    } else {
        int i = (b - WT_BLOCKS) * 256 + threadIdx.x;
        if (i < n_nodes) cur[i] = 0;
    }
}

__global__ void count_kernel(const int* __restrict__ ei, int* __restrict__ counts,
                             int n_edges)
{
    int e = blockIdx.x * blockDim.x + threadIdx.x;
    if (e < n_edges) atomicAdd(&counts[__ldg(&ei[n_edges + e])], 1);
}

__global__ void scan_block(const int* __restrict__ counts, int* __restrict__ excl,
                           int* __restrict__ blk_sums, int n)
{
    __shared__ int sd[1024];
    int tid = threadIdx.x;
    int i = blockIdx.x * 1024 + tid;
    int v = (i < n) ? counts[i] : 0;
    sd[tid] = v;
    __syncthreads();
#pragma unroll
    for (int off = 1; off < 1024; off <<= 1) {
        int tv = (tid >= off) ? sd[tid - off] : 0;
        __syncthreads();
        sd[tid] += tv;
        __syncthreads();
    }
    if (i < n) excl[i] = sd[tid] - v;
    if (tid == 1023) blk_sums[blockIdx.x] = sd[1023];
}

// Adds block offsets; each block recomputes the (<=64-entry) block-sum prefix
// itself, eliminating the separate scan_sums launch. excl == row_start array.
__global__ void scan_add(int* __restrict__ excl, const int* __restrict__ blk_sums,
                         int* __restrict__ cursor, int n, int nblocks)
{
    __shared__ int sd[64];
    int tid = threadIdx.x;
    if (tid < 64) sd[tid] = (tid < nblocks) ? blk_sums[tid] : 0;
    __syncthreads();
#pragma unroll
    for (int off = 1; off < 64; off <<= 1) {
        int tv = 0;
        if (tid < 64 && tid >= off) tv = sd[tid - off];
        __syncthreads();
        if (tid < 64) sd[tid] += tv;
        __syncthreads();
    }
    int boff = (blockIdx.x == 0) ? 0 : sd[blockIdx.x - 1];   // exclusive prefix
    int i = blockIdx.x * 1024 + tid;
    if (i < n) {
        int v = excl[i] + boff;
        excl[i] = v;
        cursor[i] = v;
    }
    if (blockIdx.x == (unsigned)(nblocks - 1) && tid == 0)
        excl[n] = sd[nblocks - 1];                            // total edge count
}

__global__ void fill_kernel(const int* __restrict__ ei, int* __restrict__ cursor,
                            int* __restrict__ csr_src, int n_edges)
{
    int e = blockIdx.x * blockDim.x + threadIdx.x;
    if (e < n_edges) {
        int d = __ldg(&ei[n_edges + e]);
        int s = __ldg(&ei[e]);
        int pos = atomicAdd(&cursor[d], 1);
        csr_src[pos] = s;
    }
}

// ===================== Pull aggregation (includes self) ====================
__global__ void pull128_kernel(const float* __restrict__ feat,
                               const int* __restrict__ row_start,
                               const int* __restrict__ csr_src,
                               float* __restrict__ out, int n_nodes)
{
    int node = (blockIdx.x * blockDim.x + threadIdx.x) >> 5;
    int lane = threadIdx.x & 31;
    if (node >= n_nodes) return;
    int e0 = __ldg(&row_start[node]);
    int e1 = __ldg(&row_start[node + 1]);
    float4 acc = __ldg(reinterpret_cast<const float4*>(feat + (size_t)node * 128) + lane);
    int e = e0;
    for (; e + 3 < e1; e += 4) {
        int s0 = __ldg(&csr_src[e]);
        int s1 = __ldg(&csr_src[e + 1]);
        int s2 = __ldg(&csr_src[e + 2]);
        int s3 = __ldg(&csr_src[e + 3]);
        float4 v0 = __ldg(reinterpret_cast<const float4*>(feat + (size_t)s0 * 128) + lane);
        float4 v1 = __ldg(reinterpret_cast<const float4*>(feat + (size_t)s1 * 128) + lane);
        float4 v2 = __ldg(reinterpret_cast<const float4*>(feat + (size_t)s2 * 128) + lane);
        float4 v3 = __ldg(reinterpret_cast<const float4*>(feat + (size_t)s3 * 128) + lane);
        acc.x += (v0.x + v1.x) + (v2.x + v3.x);
        acc.y += (v0.y + v1.y) + (v2.y + v3.y);
        acc.z += (v0.z + v1.z) + (v2.z + v3.z);
        acc.w += (v0.w + v1.w) + (v2.w + v3.w);
    }
    for (; e < e1; e++) {
        int s = __ldg(&csr_src[e]);
        float4 v = __ldg(reinterpret_cast<const float4*>(feat + (size_t)s * 128) + lane);
        acc.x += v.x; acc.y += v.y; acc.z += v.z; acc.w += v.w;
    }
    *reinterpret_cast<float4*>(out + (size_t)node * 128 + lane * 4) = acc;
}

__global__ void pull64_kernel(const float* __restrict__ feat,
                              const int* __restrict__ row_start,
                              const int* __restrict__ csr_src,
                              float* __restrict__ out, int n_nodes)
{
    int gw   = (blockIdx.x * blockDim.x + threadIdx.x) >> 5;
    int lane = threadIdx.x & 31;
    int node = gw * 2 + (lane >> 4);
    int sub  = lane & 15;
    if (node >= n_nodes) return;
    int e0 = __ldg(&row_start[node]);
    int e1 = __ldg(&row_start[node + 1]);
    float4 acc = __ldg(reinterpret_cast<const float4*>(feat + (size_t)node * 64) + sub);
    int e = e0;
    for (; e + 3 < e1; e += 4) {
        int s0 = __ldg(&csr_src[e]);
        int s1 = __ldg(&csr_src[e + 1]);
        int s2 = __ldg(&csr_src[e + 2]);
        int s3 = __ldg(&csr_src[e + 3]);
        float4 v0 = __ldg(reinterpret_cast<const float4*>(feat + (size_t)s0 * 64) + sub);
        float4 v1 = __ldg(reinterpret_cast<const float4*>(feat + (size_t)s1 * 64) + sub);
        float4 v2 = __ldg(reinterpret_cast<const float4*>(feat + (size_t)s2 * 64) + sub);
        float4 v3 = __ldg(reinterpret_cast<const float4*>(feat + (size_t)s3 * 64) + sub);
        acc.x += (v0.x + v1.x) + (v2.x + v3.x);
        acc.y += (v0.y + v1.y) + (v2.y + v3.y);
        acc.z += (v0.z + v1.z) + (v2.z + v3.z);
        acc.w += (v0.w + v1.w) + (v2.w + v3.w);
    }
    for (; e < e1; e++) {
        int s = __ldg(&csr_src[e]);
        float4 v = __ldg(reinterpret_cast<const float4*>(feat + (size_t)s * 64) + sub);
        acc.x += v.x; acc.y += v.y; acc.z += v.z; acc.w += v.w;
    }
    *reinterpret_cast<float4*>(out + (size_t)node * 64 + sub * 4) = acc;
}

// ===================== mma.sync GEMM (BM=64) ====================
template <int K, int N, int WM, bool RELU, bool RESID>
__global__ __launch_bounds__(256)
void gemm_mma(const float* __restrict__ X,
              const __nv_bfloat16* __restrict__ WT_hi,
              const __nv_bfloat16* __restrict__ WT_lo,
              const float* __restrict__ Bv,
              const float* __restrict__ RES,
              float* __restrict__ OUT,
              int nrows)
{
    constexpr int BM = 64;
    constexpr int SK = K + 8;
    constexpr int WNW = 8 / WM;
    constexpr int MT = BM / WM / 16;
    constexpr int WN = N / WNW;
    constexpr int NT = WN / 8;
    constexpr int KS = K / 16;

    extern __shared__ __nv_bfloat16 smem[];
    __nv_bfloat16* Ah = smem;
    __nv_bfloat16* Al = Ah + BM * SK;
    __nv_bfloat16* Bh = Al + BM * SK;
    __nv_bfloat16* Bl = Bh + (size_t)N * SK;

    const int t = threadIdx.x;
    const int lane = t & 31;
    const int wid = t >> 5;
    const int wm = wid % WM;
    const int wn = wid / WM;
    const int row0 = blockIdx.x * BM;

    for (int i = t; i < N * K / 8; i += 256) {
        int n = (i * 8) / K;
        int k = (i * 8) % K;
        uint4 vh = __ldg(reinterpret_cast<const uint4*>(WT_hi) + i);
        uint4 vl = __ldg(reinterpret_cast<const uint4*>(WT_lo) + i);
        *reinterpret_cast<uint4*>(&Bh[n * SK + k]) = vh;
        *reinterpret_cast<uint4*>(&Bl[n * SK + k]) = vl;
    }

    for (int i = t; i < BM * K / 4; i += 256) {
        int row = (i * 4) / K;
        int col = (i * 4) % K;
        float4 v = make_float4(0.f, 0.f, 0.f, 0.f);
        int gr = row0 + row;
        if (gr < nrows)
            v = __ldg(reinterpret_cast<const float4*>(X + (size_t)gr * K) + (col >> 2));
        __nv_bfloat16 h0, h1, h2, h3, l0, l1, l2, l3;
        split2(v.x, h0, l0); split2(v.y, h1, l1);
        split2(v.z, h2, l2); split2(v.w, h3, l3);
        int o = row * SK + col;
        *reinterpret_cast<uint32_t*>(&Ah[o])     = pack_bf2(h0, h1);
        *reinterpret_cast<uint32_t*>(&Ah[o + 2]) = pack_bf2(h2, h3);
        *reinterpret_cast<uint32_t*>(&Al[o])     = pack_bf2(l0, l1);
        *reinterpret_cast<uint32_t*>(&Al[o + 2]) = pack_bf2(l2, l3);
    }
    __syncthreads();

    float acc[MT][NT][4] = {};
    for (int ks = 0; ks < KS; ks++) {
        const int k0 = ks * 16;
        const int tt = lane >> 3;
        const int tr = lane & 7;

        uint32_t a[MT][2][4];
#pragma unroll
        for (int mt = 0; mt < MT; mt++) {
            int r = wm * (MT * 16) + mt * 16 + (tt & 1) * 8 + tr;
            int c = k0 + (tt >> 1) * 8;
            LDMATRIX_X4(a[mt][0][0], a[mt][0][1], a[mt][0][2], a[mt][0][3],
                        smem_u32(&Ah[r * SK + c]));
            LDMATRIX_X4(a[mt][1][0], a[mt][1][1], a[mt][1][2], a[mt][1][3],
                        smem_u32(&Al[r * SK + c]));
        }

        uint32_t b[NT][2][2];
#pragma unroll
        for (int p = 0; p < NT / 2; p++) {
            int n = wn * WN + p * 16 + (tt >> 1) * 8 + tr;
            int c = k0 + (tt & 1) * 8;
            uint32_t r0, r1, r2, r3;
            LDMATRIX_X4(r0, r1, r2, r3, smem_u32(&Bh[n * SK + c]));
            b[2*p][0][0] = r0; b[2*p][0][1] = r1;
            b[2*p+1][0][0] = r2; b[2*p+1][0][1] = r3;
            LDMATRIX_X4(r0, r1, r2, r3, smem_u32(&Bl[n * SK + c]));
            b[2*p][1][0] = r0; b[2*p][1][1] = r1;
            b[2*p+1][1][0] = r2; b[2*p+1][1][1] = r3;
        }

#pragma unroll
        for (int mt = 0; mt < MT; mt++)
#pragma unroll
            for (int nt = 0; nt < NT; nt++)
                mma_bf16(acc[mt][nt], a[mt][0], b[nt][0]);
#pragma unroll
        for (int mt = 0; mt < MT; mt++)
#pragma unroll
            for (int nt = 0; nt < NT; nt++)
                mma_bf16(acc[mt][nt], a[mt][0], b[nt][1]);
#pragma unroll
        for (int mt = 0; mt < MT; mt++)
#pragma unroll
            for (int nt = 0; nt < NT; nt++)
                mma_bf16(acc[mt][nt], a[mt][1], b[nt][0]);
    }

#pragma unroll
    for (int mt = 0; mt < MT; mt++) {
        int r_lo = row0 + wm * (MT * 16) + mt * 16 + (lane >> 2);
        int r_hi = r_lo + 8;
#pragma unroll
        for (int nt = 0; nt < NT; nt++) {
            int col = wn * WN + nt * 8 + (lane & 3) * 2;
            float bi0 = __ldg(&Bv[col]);
            float bi1 = __ldg(&Bv[col + 1]);
            if (r_lo < nrows) {
                float o0 = acc[mt][nt][0] + bi0;
                float o1 = acc[mt][nt][1] + bi1;
                if (RELU) { o0 = fmaxf(o0, 0.f); o1 = fmaxf(o1, 0.f); }
                if (RESID) {
                    float2 rr = __ldg(reinterpret_cast<const float2*>(RES + (size_t)r_lo * N + col));
                    o0 += rr.x; o1 += rr.y;
                }
                *reinterpret_cast<float2*>(OUT + (size_t)r_lo * N + col) = make_float2(o0, o1);
            }
            if (r_hi < nrows) {
                float o0 = acc[mt][nt][2] + bi0;
                float o1 = acc[mt][nt][3] + bi1;
                if (RELU) { o0 = fmaxf(o0, 0.f); o1 = fmaxf(o1, 0.f); }
                if (RESID) {
                    float2 rr = __ldg(reinterpret_cast<const float2*>(RES + (size_t)r_hi * N + col));
                    o0 += rr.x; o1 += rr.y;
                }
                *reinterpret_cast<float2*>(OUT + (size_t)r_hi * N + col) = make_float2(o0, o1);
            }
        }
    }
}

// ===================== Fused layer-2 GEMM + projection ====================
__global__ __launch_bounds__(256)
void gemm_l2_proj(const float* __restrict__ X,
                  const __nv_bfloat16* __restrict__ W2T_hi,
                  const __nv_bfloat16* __restrict__ W2T_lo,
                  const float* __restrict__ b2,
                  const float* __restrict__ RES,
                  const __nv_bfloat16* __restrict__ WpT_hi,
                  const __nv_bfloat16* __restrict__ WpT_lo,
                  const float* __restrict__ bp,
                  float* __restrict__ OUT,
                  int nrows)
{
    constexpr int BM = 64, K = 128, N = 128, NP = 32;
    constexpr int SK = K + 8;
    constexpr int KS = K / 16;
    constexpr int WM1 = 2, MT1 = 2, WN1 = 32, NT1 = 4;
    constexpr int WN2 = 16, NT2 = 2;

    extern __shared__ __nv_bfloat16 smem[];
    __nv_bfloat16* Ah = smem;
    __nv_bfloat16* Al = Ah + BM * SK;
    __nv_bfloat16* Bh = Al + BM * SK;
    __nv_bfloat16* Bl = Bh + (size_t)N * SK;

    const int t = threadIdx.x;
    const int lane = t & 31;
    const int wid = t >> 5;
    const int row0 = blockIdx.x * BM;
    const int wm1 = wid % WM1, wn1 = wid / WM1;

    for (int i = t; i < N * K / 8; i += 256) {
        int n = (i * 8) / K;
        int k = (i * 8) % K;
        *reinterpret_cast<uint4*>(&Bh[n * SK + k]) = __ldg(reinterpret_cast<const uint4*>(W2T_hi) + i);
        *reinterpret_cast<uint4*>(&Bl[n * SK + k]) = __ldg(reinterpret_cast<const uint4*>(W2T_lo) + i);
    }
    for (int i = t; i < BM * K / 4; i += 256) {
        int row = (i * 4) / K;
        int col = (i * 4) % K;
        float4 v = make_float4(0.f, 0.f, 0.f, 0.f);
        int gr = row0 + row;
        if (gr < nrows)
            v = __ldg(reinterpret_cast<const float4*>(X + (size_t)gr * K) + (col >> 2));
        __nv_bfloat16 h0, h1, h2, h3, l0, l1, l2, l3;
        split2(v.x, h0, l0); split2(v.y, h1, l1);
        split2(v.z, h2, l2); split2(v.w, h3, l3);
        int o = row * SK + col;
        *reinterpret_cast<uint32_t*>(&Ah[o])     = pack_bf2(h0, h1);
        *reinterpret_cast<uint32_t*>(&Ah[o + 2]) = pack_bf2(h2, h3);
        *reinterpret_cast<uint32_t*>(&Al[o])     = pack_bf2(l0, l1);
        *reinterpret_cast<uint32_t*>(&Al[o + 2]) = pack_bf2(l2, l3);
    }
    __syncthreads();

    float acc[MT1][NT1][4] = {};
    for (int ks = 0; ks < KS; ks++) {
        const int k0 = ks * 16;
        const int tt = lane >> 3;
        const int tr = lane & 7;

        uint32_t a[MT1][2][4];
#pragma unroll
        for (int mt = 0; mt < MT1; mt++) {
            int r = wm1 * 32 + mt * 16 + (tt & 1) * 8 + tr;
            int c = k0 + (tt >> 1) * 8;
            LDMATRIX_X4(a[mt][0][0], a[mt][0][1], a[mt][0][2], a[mt][0][3],
                        smem_u32(&Ah[r * SK + c]));
            LDMATRIX_X4(a[mt][1][0], a[mt][1][1], a[mt][1][2], a[mt][1][3],
                        smem_u32(&Al[r * SK + c]));
        }
        uint32_t b[NT1][2][2];
#pragma unroll
        for (int p = 0; p < NT1 / 2; p++) {
            int n = wn1 * WN1 + p * 16 + (tt >> 1) * 8 + tr;
            int c = k0 + (tt & 1) * 8;
            uint32_t r0, r1, r2, r3;
            LDMATRIX_X4(r0, r1, r2, r3, smem_u32(&Bh[n * SK + c]));
            b[2*p][0][0] = r0; b[2*p][0][1] = r1;
            b[2*p+1][0][0] = r2; b[2*p+1][0][1] = r3;
            LDMATRIX_X4(r0, r1, r2, r3, smem_u32(&Bl[n * SK + c]));
            b[2*p][1][0] = r0; b[2*p][1][1] = r1;
            b[2*p+1][1][0] = r2; b[2*p+1][1][1] = r3;
        }
#pragma unroll
        for (int mt = 0; mt < MT1; mt++)
#pragma unroll
            for (int nt = 0; nt < NT1; nt++)
                mma_bf16(acc[mt][nt], a[mt][0], b[nt][0]);
#pragma unroll
        for (int mt = 0; mt < MT1; mt++)
#pragma unroll
            for (int nt = 0; nt < NT1; nt++)
                mma_bf16(acc[mt][nt], a[mt][0], b[nt][1]);
#pragma unroll
        for (int mt = 0; mt < MT1; mt++)
#pragma unroll
            for (int nt = 0; nt < NT1; nt++)
                mma_bf16(acc[mt][nt], a[mt][1], b[nt][0]);
    }
    __syncthreads();

#pragma unroll
    for (int mt = 0; mt < MT1; mt++) {
        int lr_lo = wm1 * 32 + mt * 16 + (lane >> 2);
        int lr_hi = lr_lo + 8;
#pragma unroll
        for (int nt = 0; nt < NT1; nt++) {
            int col = wn1 * WN1 + nt * 8 + (lane & 3) * 2;
            float bi0 = __ldg(&b2[col]);
            float bi1 = __ldg(&b2[col + 1]);
            {
                int gr = row0 + lr_lo;
                float o0 = fmaxf(acc[mt][nt][0] + bi0, 0.f);
                float o1 = fmaxf(acc[mt][nt][1] + bi1, 0.f);
                if (gr < nrows) {
                    float2 rr = __ldg(reinterpret_cast<const float2*>(RES + (size_t)gr * N + col));
                    o0 += rr.x; o1 += rr.y;
                }
                __nv_bfloat16 h0, h1, l0, l1;
                split2(o0, h0, l0); split2(o1, h1, l1);
                int o = lr_lo * SK + col;
                *reinterpret_cast<uint32_t*>(&Ah[o]) = pack_bf2(h0, h1);
                *reinterpret_cast<uint32_t*>(&Al[o]) = pack_bf2(l0, l1);
            }
            {
                int gr = row0 + lr_hi;
                float o0 = fmaxf(acc[mt][nt][2] + bi0, 0.f);
                float o1 = fmaxf(acc[mt][nt][3] + bi1, 0.f);
                if (gr < nrows) {
                    float2 rr = __ldg(reinterpret_cast<const float2*>(RES + (size_t)gr * N + col));
                    o0 += rr.x; o1 += rr.y;
                }
                __nv_bfloat16 h0, h1, l0, l1;
                split2(o0, h0, l0); split2(o1, h1, l1);
                int o = lr_hi * SK + col;
                *reinterpret_cast<uint32_t*>(&Ah[o]) = pack_bf2(h0, h1);
                *reinterpret_cast<uint32_t*>(&Al[o]) = pack_bf2(l0, l1);
            }
        }
    }

    for (int i = t; i < NP * K / 8; i += 256) {
        int n = (i * 8) / K;
        int k = (i * 8) % K;
        *reinterpret_cast<uint4*>(&Bh[n * SK + k]) = __ldg(reinterpret_cast<const uint4*>(WpT_hi) + i);
        *reinterpret_cast<uint4*>(&Bl[n * SK + k]) = __ldg(reinterpret_cast<const uint4*>(WpT_lo) + i);
    }
    __syncthreads();

    const int wm2 = wid % 4, wn2 = wid / 4;
    float acc2[NT2][4] = {};
    for (int ks = 0; ks < KS; ks++) {
        const int k0 = ks * 16;
        const int tt = lane >> 3;
        const int tr = lane & 7;

        uint32_t a[2][4];
        {
            int r = wm2 * 16 + (tt & 1) * 8 + tr;
            int c = k0 + (tt >> 1) * 8;
            LDMATRIX_X4(a[0][0], a[0][1], a[0][2], a[0][3], smem_u32(&Ah[r * SK + c]));
            LDMATRIX_X4(a[1][0], a[1][1], a[1][2], a[1][3], smem_u32(&Al[r * SK + c]));
        }
        uint32_t b[NT2][2][2];
        {
            int n = wn2 * WN2 + (tt >> 1) * 8 + tr;
            int c = k0 + (tt & 1) * 8;
            uint32_t r0, r1, r2, r3;
            LDMATRIX_X4(r0, r1, r2, r3, smem_u32(&Bh[n * SK + c]));
            b[0][0][0] = r0; b[0][0][1] = r1;
            b[1][0][0] = r2; b[1][0][1] = r3;
            LDMATRIX_X4(r0, r1, r2, r3, smem_u32(&Bl[n * SK + c]));
            b[0][1][0] = r0; b[0][1][1] = r1;
            b[1][1][0] = r2; b[1][1][1] = r3;
        }
#pragma unroll
        for (int nt = 0; nt < NT2; nt++) mma_bf16(acc2[nt], a[0], b[nt][0]);
#pragma unroll
        for (int nt = 0; nt < NT2; nt++) mma_bf16(acc2[nt], a[0], b[nt][1]);
#pragma unroll
        for (int nt = 0; nt < NT2; nt++) mma_bf16(acc2[nt], a[1], b[nt][0]);
    }

    {
        int r_lo = row0 + wm2 * 16 + (lane >> 2);
        int r_hi = r_lo + 8;
#pragma unroll
        for (int nt = 0; nt < NT2; nt++) {
            int col = wn2 * WN2 + nt * 8 + (lane & 3) * 2;
            float bi0 = __ldg(&bp[col]);
            float bi1 = __ldg(&bp[col + 1]);
            if (r_lo < nrows)
                *reinterpret_cast<float2*>(OUT + (size_t)r_lo * NP + col) =
                    make_float2(acc2[nt][0] + bi0, acc2[nt][1] + bi1);
            if (r_hi < nrows)
                *reinterpret_cast<float2*>(OUT + (size_t)r_hi * NP + col) =
                    make_float2(acc2[nt][2] + bi0, acc2[nt][3] + bi1);
        }
    }
}

// ===================== Launch ====================
extern "C" void kernel_launch(void* const* d_in, const int* in_sizes, int n_in,
                              void* d_out, int out_size)
{
    const float* x  = (const float*)d_in[0];
    const int*   ei = (const int*)d_in[1];
    const float* W0 = (const float*)d_in[2];
    const float* b0 = (const float*)d_in[3];
    const float* W1 = (const float*)d_in[4];
    const float* b1 = (const float*)d_in[5];
    const float* W2 = (const float*)d_in[6];
    const float* b2 = (const float*)d_in[7];
    const float* Wp = (const float*)d_in[8];
    const float* bp = (const float*)d_in[9];
    float* out = (float*)d_out;

    const int n_nodes = in_sizes[0] / 64;
    const int n_edges = in_sizes[1] / 2;
    const int nblocks = (n_nodes + 1023) / 1024;

    float *sum, *h0, *h1;
    int *row, *cur, *csr, *blk;
    __nv_bfloat16 *wthi, *wtlo;
    cudaGetSymbolAddress((void**)&sum,  g_sum);
    cudaGetSymbolAddress((void**)&h0,   g_h0);
    cudaGetSymbolAddress((void**)&h1,   g_h1);
    cudaGetSymbolAddress((void**)&row,  g_row);
    cudaGetSymbolAddress((void**)&cur,  g_cur);
    cudaGetSymbolAddress((void**)&csr,  g_csr);
    cudaGetSymbolAddress((void**)&blk,  g_blk);
    cudaGetSymbolAddress((void**)&wthi, g_wthi);
    cudaGetSymbolAddress((void**)&wtlo, g_wtlo);

    const int eb = (n_edges + 255) / 256;
    const int prep_blocks = WT_BLOCKS + (n_nodes + 255) / 256;
    const int pull128_blocks = (n_nodes + 7) / 8;
    const int pull64_blocks  = (n_nodes + 15) / 16;
    const int gemm_blocks    = (n_nodes + 63) / 64;

    const int smem_l0 = (2 * 64 * 72  + 2 * 128 * 72)  * 2;  // 55296
    const int smem_l  = (2 * 64 * 136 + 2 * 128 * 136) * 2;  // 104448
    cudaFuncSetAttribute(gemm_mma<64, 128, 2, true, false>,
                         cudaFuncAttributeMaxDynamicSharedMemorySize, smem_l0);
    cudaFuncSetAttribute(gemm_mma<128, 128, 2, true, true>,
                         cudaFuncAttributeMaxDynamicSharedMemorySize, smem_l);
    cudaFuncSetAttribute(gemm_l2_proj,
                         cudaFuncAttributeMaxDynamicSharedMemorySize, smem_l);

    // ---- Prologue: prep (wtrans + zero cur) -> count -> scan(x2) -> fill ----
    prep_kernel<<<prep_blocks, 256>>>(W0, W1, W2, Wp, wthi, wtlo, cur, n_nodes);
    count_kernel<<<eb, 256>>>(ei, cur, n_edges);
    scan_block<<<nblocks, 1024>>>(cur, row, blk, n_nodes);
    scan_add<<<nblocks, 1024>>>(row, blk, cur, n_nodes, nblocks);
    fill_kernel<<<eb, 256>>>(ei, cur, csr, n_edges);

    // ---- Layer 0 ----
    pull64_kernel<<<pull64_blocks, 256>>>(x, row, csr, sum, n_nodes);
    gemm_mma<64, 128, 2, true, false>
        <<<gemm_blocks, 256, smem_l0>>>(sum, wthi + WT0_OFF, wtlo + WT0_OFF, b0, nullptr, h0, n_nodes);

    // ---- Layer 1 ----
    pull128_kernel<<<pull128_blocks, 256>>>(h0, row, csr, sum, n_nodes);
    gemm_mma<128, 128, 2, true, true>
        <<<gemm_blocks, 256, smem_l>>>(sum, wthi + WT1_OFF, wtlo + WT1_OFF, b1, h0, h1, n_nodes);

    // ---- Layer 2 + projection (fused) ----
    pull128_kernel<<<pull128_blocks, 256>>>(h1, row, csr, sum, n_nodes);
    gemm_l2_proj<<<gemm_blocks, 256, smem_l>>>(sum, wthi + WT2_OFF, wtlo + WT2_OFF, b2, h1,
                                               wthi + WTP_OFF, wtlo + WTP_OFF, bp, out, n_nodes);
}